// round 15
// baseline (speedup 1.0000x reference)
#include <cuda_runtime.h>
#include <cstdint>

#define NB    131072
#define DC    1029
#define TT    1024
#define H1N   64
#define H2N   32
#define KTOT  1028
#define KC    32
#define NCH   33              // 33*32 = 1056 padded K
#define MT    128             // rows per CTA
#define NT    256             // 8 warps, each m16 x n64
#define B_ST  8192            // bytes per B stage
#define SMEM_DYN 98304        // 12-slot B ring (3 groups x 4 chunks)
#define H_STRIDE 68

__device__ float g_row_mean[TT];
__device__ __align__(16) float g_w1f[NCH * 2048];   // pre-packed, pre-swizzled tf32 B frags

// ---------------- helpers ----------------
__device__ __forceinline__ uint32_t tf32r(float f) {
    uint32_t u;
    asm("cvt.rna.tf32.f32 %0, %1;" : "=r"(u) : "f"(f));
    return u;
}
__device__ __forceinline__ void mma_tf32(float* d, const uint32_t* a, uint32_t b0, uint32_t b1) {
    asm volatile(
        "mma.sync.aligned.m16n8k8.row.col.f32.tf32.tf32.f32 "
        "{%0,%1,%2,%3}, {%4,%5,%6,%7}, {%8,%9}, {%0,%1,%2,%3};"
        : "+f"(d[0]), "+f"(d[1]), "+f"(d[2]), "+f"(d[3])
        : "r"(a[0]), "r"(a[1]), "r"(a[2]), "r"(a[3]), "r"(b0), "r"(b1));
}
__device__ __forceinline__ uint32_t smem_u32(const void* p) {
    uint32_t a;
    asm("{ .reg .u64 t; cvta.to.shared.u64 t, %1; cvt.u32.u64 %0, t; }" : "=r"(a) : "l"(p));
    return a;
}
__device__ __forceinline__ void cp16(uint32_t dst, const float* src) {
    asm volatile("cp.async.ca.shared.global [%0], [%1], 16;"
                 :: "r"(dst), "l"(__cvta_generic_to_global(src)) : "memory");
}

// ---------------- merged prep kernel (identical pack layout to R5/R10) ----------------
__global__ void prep_kernel(const float* __restrict__ con, const float* __restrict__ w1) {
    if (blockIdx.x < TT) {
        int t = blockIdx.x;
        float s = 0.f;
        for (int j = threadIdx.x; j < TT; j += blockDim.x)
            s += con[(size_t)t * TT + j];
#pragma unroll
        for (int o = 16; o > 0; o >>= 1) s += __shfl_down_sync(0xffffffffu, s, o);
        __shared__ float red[8];
        if ((threadIdx.x & 31) == 0) red[threadIdx.x >> 5] = s;
        __syncthreads();
        if (threadIdx.x == 0) {
            float tot = 0.f;
#pragma unroll
            for (int w = 0; w < 8; w++) tot += red[w];
            g_row_mean[t] = tot * (1.0f / (float)TT);
        }
    } else {
        int idx = (blockIdx.x - TT) * blockDim.x + threadIdx.x;
        if (idx >= NCH * 2048) return;
        int ch = idx >> 11;
        int w  = idx & 2047;
        int g  = w >> 2, e = w & 3;
        int kt = g >> 7;
        int lane = (g >> 2) & 31;
        int s = g & 3;
        int i = s ^ (lane & 3) ^ ((lane >> 2) & 1);
        int nt = 2 * i + (e >> 1);
        int jj = e & 1;
        int k = ch * 32 + kt * 8 + (lane & 3) + jj * 4;
        int n = nt * 8 + (lane >> 2);
        float v = 0.f;
        if (k < 4)          v = w1[k * H1N + n];
        else if (k < KTOT)  v = w1[(k + 1) * H1N + n];
        g_w1f[idx] = __uint_as_float(tf32r(v));
    }
}

// ---------------- fused main kernel ----------------
__global__ __launch_bounds__(NT, 2)
void fused_mma(const float* __restrict__ x,
               const float* __restrict__ w1,
               const float* __restrict__ b1,
               const float* __restrict__ w2,
               const float* __restrict__ b2,
               const float* __restrict__ w3,
               const float* __restrict__ b3,
               float* __restrict__ out)
{
    extern __shared__ __align__(16) char smem[];
    __shared__ __align__(16) float s_w2[H1N * H2N];
    __shared__ float s_w14[H1N], s_b1[H1N], s_b2[H2N], s_w3[H2N];
    __shared__ float s_den[MT], s_ceff[MT];
    __shared__ int   s_mi[MT];

    const uint32_t sdyn = smem_u32(smem);
    const int tid  = threadIdx.x;
    const int w    = tid >> 5;
    const int lane = tid & 31;
    const int rA   = lane >> 2;
    const int cA   = lane & 3;
    const int row0 = blockIdx.x * MT;

    // stage constants
#pragma unroll
    for (int i = tid; i < H1N * H2N; i += NT) s_w2[i] = __ldg(w2 + i);
    if (tid < H1N) { s_w14[tid] = __ldg(w1 + 4 * H1N + tid); s_b1[tid] = __ldg(b1 + tid); }
    if (tid < H2N) { s_b2[tid] = __ldg(b2 + tid); s_w3[tid] = __ldg(w3 + tid); }

    // B producer: one commit-group per 4-chunk group; group g -> slots (g%3)*4 ..+3
    auto produceGroup = [&](int g) {
        const uint32_t base = sdyn + (uint32_t)(g % 3) * (4u * B_ST);
#pragma unroll
        for (int q = 0; q < 4; q++) {
            const int ch = 4 * g + q;
            if (ch < NCH) {
                const uint32_t slot = base + (uint32_t)q * B_ST;
                const float* src = g_w1f + (size_t)ch * 2048;
                cp16(slot + (uint32_t)tid * 16u, src + (size_t)tid * 4);
                cp16(slot + (uint32_t)(tid + NT) * 16u, src + (size_t)(tid + NT) * 4);
            }
        }
        asm volatile("cp.async.commit_group;" ::: "memory");
    };

    // A loaders: 16 floats, fragment layout idx = kt*4 + hh*2 + r01
    const float* xp0 = x + (size_t)(row0 + w * 16 + rA) * DC + cA;
    const float* xp1 = xp0 + 8 * (size_t)DC;
    auto loadA = [&](int ch, float* dst) {              // chunks 0..31: no bounds check
        const int kb = ch * KC;
#pragma unroll
        for (int kt = 0; kt < 4; kt++)
#pragma unroll
            for (int hh = 0; hh < 2; hh++) {
                const int ko = kb + kt * 8 + hh * 4;
                dst[kt * 4 + hh * 2 + 0] = __ldg(xp0 + ko);
                dst[kt * 4 + hh * 2 + 1] = __ldg(xp1 + ko);
            }
    };
    auto loadA_g = [&](int ch, float* dst) {            // chunk 32: guarded
        const int kb = ch * KC;
#pragma unroll
        for (int kt = 0; kt < 4; kt++)
#pragma unroll
            for (int hh = 0; hh < 2; hh++) {
                const int ko = kb + kt * 8 + hh * 4;
                const bool ok = (ko + cA) < KTOT;
                dst[kt * 4 + hh * 2 + 0] = ok ? __ldg(xp0 + ko) : 0.f;
                dst[kt * 4 + hh * 2 + 1] = ok ? __ldg(xp1 + ko) : 0.f;
            }
    };

    float amv[2];
    int   ami[2];
    amv[0] = amv[1] = __int_as_float(0xff800000);
    ami[0] = ami[1] = 0;

    float acc[8][4];
#pragma unroll
    for (int nt = 0; nt < 8; nt++)
#pragma unroll
        for (int j = 0; j < 4; j++) acc[nt][j] = 0.f;

    // argmax, predicate-free (chunks 1..31: kg-4 always in [0,1024))
    auto amaxMid = [&](int ch, const float* CUR) {
        const int kb = ch * KC;
#pragma unroll
        for (int kt = 0; kt < 4; kt++)
#pragma unroll
            for (int hh = 0; hh < 2; hh++) {
                const int kg = kb + kt * 8 + cA + hh * 4;
                const float v0 = CUR[kt * 4 + hh * 2 + 0];
                const float v1 = CUR[kt * 4 + hh * 2 + 1];
                if (v0 > amv[0]) { amv[0] = v0; ami[0] = kg - 4; }
                if (v1 > amv[1]) { amv[1] = v1; ami[1] = kg - 4; }
            }
    };

    // convert + B LDS + 32 MMAs (slot base passed in)
    auto mmaPart = [&](uint32_t slotB, const float* CUR) {
        uint32_t au[16];
#pragma unroll
        for (int i = 0; i < 16; i++) au[i] = tf32r(CUR[i]);
        const uint32_t bbase = slotB + (uint32_t)lane * 64u;
        const int sw = cA ^ (rA & 1);
#pragma unroll
        for (int kt = 0; kt < 4; kt++) {
            const uint32_t* a = au + kt * 4;
#pragma unroll
            for (int i = 0; i < 4; i++) {
                uint4 q;
                const uint32_t baddr = bbase + (uint32_t)kt * 2048u
                                     + (uint32_t)((i ^ sw) << 4);
                asm volatile("ld.shared.v4.u32 {%0,%1,%2,%3}, [%4];"
                             : "=r"(q.x), "=r"(q.y), "=r"(q.z), "=r"(q.w) : "r"(baddr));
                mma_tf32(acc[2 * i + 0], a, q.x, q.y);
                mma_tf32(acc[2 * i + 1], a, q.z, q.w);
            }
        }
    };

    float bufA[16], bufB[16];

    // prologue: 2 B groups in flight; A chunk 0 in regs
    produceGroup(0);
    produceGroup(1);
    loadA(0, bufA);

    // ---- group 0 (chunk 0 special: density + argmax excluding kt0/hh0) ----
    {
        asm volatile("cp.async.wait_group 1;" ::: "memory");
        __syncthreads();
        produceGroup(2);
        const uint32_t gb = sdyn;   // (0%3)*4*B_ST

        loadA(1, bufB);
        // chunk 0 argmax: skip (kt=0,hh=0) quad (kg = cA < 4)
#pragma unroll
        for (int kt = 0; kt < 4; kt++)
#pragma unroll
            for (int hh = 0; hh < 2; hh++) {
                if (kt == 0 && hh == 0) continue;
                const int kg = kt * 8 + cA + hh * 4;
                const float v0 = bufA[kt * 4 + hh * 2 + 0];
                const float v1 = bufA[kt * 4 + hh * 2 + 1];
                if (v0 > amv[0]) { amv[0] = v0; ami[0] = kg - 4; }
                if (v1 > amv[1]) { amv[1] = v1; ami[1] = kg - 4; }
            }
        if (cA == 0) {
            s_den[w * 16 + rA]     = bufA[0];
            s_den[w * 16 + rA + 8] = bufA[1];
        }
        mmaPart(gb, bufA);

        loadA(2, bufA);
        amaxMid(1, bufB); mmaPart(gb + B_ST, bufB);
        loadA(3, bufB);
        amaxMid(2, bufA); mmaPart(gb + 2u * B_ST, bufA);
        loadA(4, bufA);
        amaxMid(3, bufB); mmaPart(gb + 3u * B_ST, bufB);
    }

    // ---- groups 1..7 (chunks 4..31, fully predicate-free) ----
#pragma unroll 1
    for (int g = 1; g <= 7; ++g) {
        asm volatile("cp.async.wait_group 1;" ::: "memory");
        __syncthreads();               // group g visible; group g-1 slots free
        produceGroup(g + 2);
        const uint32_t gb = sdyn + (uint32_t)(g % 3) * (4u * B_ST);
        const int c = 4 * g;

        loadA(c + 1, bufB);
        amaxMid(c + 0, bufA); mmaPart(gb, bufA);
        loadA(c + 2, bufA);
        amaxMid(c + 1, bufB); mmaPart(gb + B_ST, bufB);
        loadA(c + 3, bufB);
        amaxMid(c + 2, bufA); mmaPart(gb + 2u * B_ST, bufA);
        if (g < 7) loadA(c + 4, bufA); else loadA_g(32, bufA);
        amaxMid(c + 3, bufB); mmaPart(gb + 3u * B_ST, bufB);
    }

    // ---- group 8: chunk 32 only, no argmax (kg >= 1024 never wins) ----
    {
        asm volatile("cp.async.wait_group 1;" ::: "memory");
        __syncthreads();
        mmaPart(sdyn + 2u * (4u * B_ST), bufA);   // (8%3)=2, qq=0
    }

    // ---- argmax reduce across the 4 cA lanes ----
    __syncthreads();
#pragma unroll
    for (int d = 1; d < 4; d <<= 1) {
#pragma unroll
        for (int hf = 0; hf < 2; hf++) {
            float ov = __shfl_xor_sync(0xffffffffu, amv[hf], d);
            int   oi = __shfl_xor_sync(0xffffffffu, ami[hf], d);
            if (ov > amv[hf] || (ov == amv[hf] && oi < ami[hf])) { amv[hf] = ov; ami[hf] = oi; }
        }
    }
    if (cA == 0) {
        s_mi[w * 16 + rA]     = ami[0];
        s_mi[w * 16 + rA + 8] = ami[1];
    }
    __syncthreads();
    if (tid < MT) s_ceff[tid] = g_row_mean[s_mi[tid]] * s_den[tid];
    __syncthreads();

    // ---- layer-1 epilogue: +ceff*w1[4,:]+b1, relu; h -> dynamic smem ----
    float* h = (float*)smem;
    {
        const int r1 = w * 16 + rA;
        const int cb = cA * 2;
        const float ce0 = s_ceff[r1];
        const float ce1 = s_ceff[r1 + 8];
#pragma unroll
        for (int nt = 0; nt < 8; nt++) {
            const int c = nt * 8 + cb;
            const float w0 = s_w14[c], w1v = s_w14[c + 1];
            const float q0 = s_b1[c],  q1  = s_b1[c + 1];
            float2 top, bot;
            top.x = fmaxf(acc[nt][0] + ce0 * w0 + q0, 0.f);
            top.y = fmaxf(acc[nt][1] + ce0 * w1v + q1, 0.f);
            bot.x = fmaxf(acc[nt][2] + ce1 * w0 + q0, 0.f);
            bot.y = fmaxf(acc[nt][3] + ce1 * w1v + q1, 0.f);
            *reinterpret_cast<float2*>(h + (size_t)r1 * H_STRIDE + c) = top;
            *reinterpret_cast<float2*>(h + (size_t)(r1 + 8) * H_STRIDE + c) = bot;
        }
    }
    __syncthreads();

    // ---- layers 2 & 3: one thread per row ----
    if (tid < MT) {
        float a2[H2N];
#pragma unroll
        for (int j = 0; j < H2N; j++) a2[j] = s_b2[j];
        const float* hr = h + (size_t)tid * H_STRIDE;
#pragma unroll 4
        for (int k = 0; k < H1N; k++) {
            const float a = hr[k];
            const float4* w2r = reinterpret_cast<const float4*>(s_w2 + k * H2N);
#pragma unroll
            for (int qq = 0; qq < H2N / 4; qq++) {
                float4 w4 = w2r[qq];
                a2[qq * 4 + 0] += a * w4.x;
                a2[qq * 4 + 1] += a * w4.y;
                a2[qq * 4 + 2] += a * w4.z;
                a2[qq * 4 + 3] += a * w4.w;
            }
        }
        float o = __ldg(b3);
#pragma unroll
        for (int j = 0; j < H2N; j++)
            o += fmaxf(a2[j], 0.f) * s_w3[j];
        out[row0 + tid] = fmaxf(o, 0.f);
    }
}

// ---------------- launch (2 launches per call) ----------------
extern "C" void kernel_launch(void* const* d_in, const int* in_sizes, int n_in,
                              void* d_out, int out_size) {
    const float* x   = (const float*)d_in[0];
    const float* con = (const float*)d_in[1];
    const float* w1  = (const float*)d_in[2];
    const float* b1  = (const float*)d_in[3];
    const float* w2  = (const float*)d_in[4];
    const float* b2  = (const float*)d_in[5];
    const float* w3  = (const float*)d_in[6];
    const float* b3  = (const float*)d_in[7];
    float* out = (float*)d_out;

    cudaFuncSetAttribute(fused_mma, cudaFuncAttributeMaxDynamicSharedMemorySize, SMEM_DYN);

    prep_kernel<<<TT + (NCH * 2048 + 255) / 256, 256>>>(con, w1);
    fused_mma<<<NB / MT, NT, SMEM_DYN>>>(x, w1, b1, w2, b2, w3, b3, out);
}

// round 16
// speedup vs baseline: 1.4600x; 1.4600x over previous
#include <cuda_runtime.h>
#include <cstdint>

#define NB    131072
#define DC    1029
#define TT    1024
#define H1N   64
#define H2N   32
#define KTOT  1028
#define KC    32
#define NCH   33              // 33*32 = 1056 padded K
#define MT    64              // rows per CTA
#define NT    128             // 4 warps, each m16 x n64
#define NSLOT 4               // B ring slots (2 pairs)
#define B_ST  8192            // bytes per B stage
#define SMEM_DYN 32768        // 4*B_ST (covers h staging 64*68*4=17408)
#define H_STRIDE 68

__device__ float g_row_mean[TT];
__device__ __align__(16) float g_w1f[NCH * 2048];   // pre-packed, pre-swizzled tf32 B frags

// ---------------- helpers ----------------
__device__ __forceinline__ uint32_t tf32r(float f) {
    uint32_t u;
    asm("cvt.rna.tf32.f32 %0, %1;" : "=r"(u) : "f"(f));
    return u;
}
__device__ __forceinline__ void mma_tf32(float* d, const uint32_t* a, uint32_t b0, uint32_t b1) {
    asm volatile(
        "mma.sync.aligned.m16n8k8.row.col.f32.tf32.tf32.f32 "
        "{%0,%1,%2,%3}, {%4,%5,%6,%7}, {%8,%9}, {%0,%1,%2,%3};"
        : "+f"(d[0]), "+f"(d[1]), "+f"(d[2]), "+f"(d[3])
        : "r"(a[0]), "r"(a[1]), "r"(a[2]), "r"(a[3]), "r"(b0), "r"(b1));
}
__device__ __forceinline__ uint32_t smem_u32(const void* p) {
    uint32_t a;
    asm("{ .reg .u64 t; cvta.to.shared.u64 t, %1; cvt.u32.u64 %0, t; }" : "=r"(a) : "l"(p));
    return a;
}
__device__ __forceinline__ void cp16(uint32_t dst, const float* src) {
    asm volatile("cp.async.ca.shared.global [%0], [%1], 16;"
                 :: "r"(dst), "l"(__cvta_generic_to_global(src)) : "memory");
}

// ---------------- merged prep kernel (identical pack layout to R5/R10) ----------------
__global__ void prep_kernel(const float* __restrict__ con, const float* __restrict__ w1) {
    if (blockIdx.x < TT) {
        int t = blockIdx.x;
        float s = 0.f;
        for (int j = threadIdx.x; j < TT; j += blockDim.x)
            s += con[(size_t)t * TT + j];
#pragma unroll
        for (int o = 16; o > 0; o >>= 1) s += __shfl_down_sync(0xffffffffu, s, o);
        __shared__ float red[8];
        if ((threadIdx.x & 31) == 0) red[threadIdx.x >> 5] = s;
        __syncthreads();
        if (threadIdx.x == 0) {
            float tot = 0.f;
#pragma unroll
            for (int w = 0; w < 8; w++) tot += red[w];
            g_row_mean[t] = tot * (1.0f / (float)TT);
        }
    } else {
        int idx = (blockIdx.x - TT) * blockDim.x + threadIdx.x;
        if (idx >= NCH * 2048) return;
        int ch = idx >> 11;
        int w  = idx & 2047;
        int g  = w >> 2, e = w & 3;
        int kt = g >> 7;
        int lane = (g >> 2) & 31;
        int s = g & 3;
        int i = s ^ (lane & 3) ^ ((lane >> 2) & 1);
        int nt = 2 * i + (e >> 1);
        int jj = e & 1;
        int k = ch * 32 + kt * 8 + (lane & 3) + jj * 4;
        int n = nt * 8 + (lane >> 2);
        float v = 0.f;
        if (k < 4)          v = w1[k * H1N + n];
        else if (k < KTOT)  v = w1[(k + 1) * H1N + n];
        g_w1f[idx] = __uint_as_float(tf32r(v));
    }
}

// ---------------- fused main kernel ----------------
__global__ __launch_bounds__(NT, 4)
void fused_mma(const float* __restrict__ x,
               const float* __restrict__ w1,
               const float* __restrict__ b1,
               const float* __restrict__ w2,
               const float* __restrict__ b2,
               const float* __restrict__ w3,
               const float* __restrict__ b3,
               float* __restrict__ out)
{
    extern __shared__ __align__(16) char smem[];
    __shared__ __align__(16) float s_w2[H1N * H2N];
    __shared__ float s_w14[H1N], s_b1[H1N], s_b2[H2N], s_w3[H2N];
    __shared__ float s_den[MT], s_ceff[MT];
    __shared__ int   s_mi[MT];

    const uint32_t sdyn = smem_u32(smem);
    const int tid  = threadIdx.x;
    const int w    = tid >> 5;
    const int lane = tid & 31;
    const int rA   = lane >> 2;
    const int cA   = lane & 3;
    const int row0 = blockIdx.x * MT;

    // stage constants
#pragma unroll
    for (int i = tid; i < H1N * H2N; i += NT) s_w2[i] = __ldg(w2 + i);
    if (tid < H1N) { s_w14[tid] = __ldg(w1 + 4 * H1N + tid); s_b1[tid] = __ldg(b1 + tid); }
    if (tid < H2N) { s_b2[tid] = __ldg(b2 + tid); s_w3[tid] = __ldg(w3 + tid); }

    // B producer: one commit-group per 2-chunk pair; pair p -> slots (p&1)*2 + {0,1}
    auto producePair = [&](int pr) {
#pragma unroll
        for (int q = 0; q < 2; q++) {
            const int ch = 2 * pr + q;
            if (ch < NCH) {
                const uint32_t slot = sdyn + (uint32_t)(((pr & 1) * 2 + q)) * B_ST;
                const float* src = g_w1f + (size_t)ch * 2048;
#pragma unroll
                for (int i = 0; i < 4; i++)
                    cp16(slot + (uint32_t)(tid + i * NT) * 16u,
                         src + (size_t)(tid + i * NT) * 4);
            }
        }
        asm volatile("cp.async.commit_group;" ::: "memory");
    };

    // A loader: 16 floats in fragment layout (idx = kt*4 + hh*2 + r)  — as R10
    const float* xp0 = x + (size_t)(row0 + w * 16 + rA) * DC + cA;
    const float* xp1 = xp0 + 8 * (size_t)DC;
    auto loadA = [&](int ch, float* dst) {
        const int kb = ch * KC;
#pragma unroll
        for (int kt = 0; kt < 4; kt++)
#pragma unroll
            for (int hh = 0; hh < 2; hh++) {
                const int kg = kb + kt * 8 + hh * 4;
                const bool ok = (kg + cA) < KTOT;
                dst[kt * 4 + hh * 2 + 0] = ok ? __ldg(xp0 + kg) : 0.f;
                dst[kt * 4 + hh * 2 + 1] = ok ? __ldg(xp1 + kg) : 0.f;
            }
    };

    float amv[2];
    int   ami[2];
    amv[0] = amv[1] = __int_as_float(0xff800000);
    ami[0] = ami[1] = 0;

    float acc[8][4];
#pragma unroll
    for (int nt = 0; nt < 8; nt++)
#pragma unroll
        for (int j = 0; j < 4; j++) acc[nt][j] = 0.f;

    // one chunk's consume: argmax + convert + B LDS + 32 MMAs  — as R10
    auto process = [&](int ch, const float* CUR) {
        const int kb = ch * KC;
#pragma unroll
        for (int kt = 0; kt < 4; kt++)
#pragma unroll
            for (int hh = 0; hh < 2; hh++) {
                const int kg = kb + kt * 8 + cA + hh * 4;
                const float v0 = CUR[kt * 4 + hh * 2 + 0];
                const float v1 = CUR[kt * 4 + hh * 2 + 1];
                if ((unsigned)(kg - 4) < 1024u) {
                    if (v0 > amv[0]) { amv[0] = v0; ami[0] = kg - 4; }
                    if (v1 > amv[1]) { amv[1] = v1; ami[1] = kg - 4; }
                }
            }
        if (ch == 0 && cA == 0) {
            s_den[w * 16 + rA]     = CUR[0];
            s_den[w * 16 + rA + 8] = CUR[1];
        }

        uint32_t au[16];
#pragma unroll
        for (int i = 0; i < 16; i++) au[i] = tf32r(CUR[i]);

        const uint32_t slotB = sdyn
            + (uint32_t)((((ch >> 1) & 1) * 2 + (ch & 1))) * B_ST;
        const uint32_t bbase = slotB + (uint32_t)lane * 64u;
        const int sw = cA ^ (rA & 1);
#pragma unroll
        for (int kt = 0; kt < 4; kt++) {
            const uint32_t* a = au + kt * 4;
#pragma unroll
            for (int i = 0; i < 4; i++) {
                uint4 q;
                const uint32_t baddr = bbase + (uint32_t)kt * 2048u
                                     + (uint32_t)((i ^ sw) << 4);
                asm volatile("ld.shared.v4.u32 {%0,%1,%2,%3}, [%4];"
                             : "=r"(q.x), "=r"(q.y), "=r"(q.z), "=r"(q.w) : "r"(baddr));
                mma_tf32(acc[2 * i + 0], a, q.x, q.y);
                mma_tf32(acc[2 * i + 1], a, q.z, q.w);
            }
        }
    };

    float bufA[16], bufB[16];

    // prologue: 1 B pair in flight; A chunk 0 in regs
    producePair(0);
    loadA(0, bufA);

#pragma unroll 1
    for (int t = 0; t < 17; ++t) {
        asm volatile("cp.async.wait_group 0;" ::: "memory");
        __syncthreads();               // pair t (chunks 2t,2t+1) visible; other slots free

        producePair(t + 1);            // next pair into the other 2 slots

        const int c0 = 2 * t, c1 = 2 * t + 1;
        if (c1 < NCH) loadA(c1, bufB);
        process(c0, bufA);
        if (c1 < NCH) {
            if (c1 + 1 < NCH) loadA(c1 + 1, bufA);
            process(c1, bufB);
        }
    }

    // ---- argmax reduce across the 4 cA lanes ----
    __syncthreads();
#pragma unroll
    for (int d = 1; d < 4; d <<= 1) {
#pragma unroll
        for (int hf = 0; hf < 2; hf++) {
            float ov = __shfl_xor_sync(0xffffffffu, amv[hf], d);
            int   oi = __shfl_xor_sync(0xffffffffu, ami[hf], d);
            if (ov > amv[hf] || (ov == amv[hf] && oi < ami[hf])) { amv[hf] = ov; ami[hf] = oi; }
        }
    }
    if (cA == 0) {
        s_mi[w * 16 + rA]     = ami[0];
        s_mi[w * 16 + rA + 8] = ami[1];
    }
    __syncthreads();
    if (tid < MT) s_ceff[tid] = g_row_mean[s_mi[tid]] * s_den[tid];
    __syncthreads();

    // ---- layer-1 epilogue: +ceff*w1[4,:]+b1, relu; h -> dynamic smem ----
    float* h = (float*)smem;
    {
        const int r1 = w * 16 + rA;
        const int cb = cA * 2;
        const float ce0 = s_ceff[r1];
        const float ce1 = s_ceff[r1 + 8];
#pragma unroll
        for (int nt = 0; nt < 8; nt++) {
            const int c = nt * 8 + cb;
            const float w0 = s_w14[c], w1v = s_w14[c + 1];
            const float q0 = s_b1[c],  q1  = s_b1[c + 1];
            float2 top, bot;
            top.x = fmaxf(acc[nt][0] + ce0 * w0 + q0, 0.f);
            top.y = fmaxf(acc[nt][1] + ce0 * w1v + q1, 0.f);
            bot.x = fmaxf(acc[nt][2] + ce1 * w0 + q0, 0.f);
            bot.y = fmaxf(acc[nt][3] + ce1 * w1v + q1, 0.f);
            *reinterpret_cast<float2*>(h + (size_t)r1 * H_STRIDE + c) = top;
            *reinterpret_cast<float2*>(h + (size_t)(r1 + 8) * H_STRIDE + c) = bot;
        }
    }
    __syncthreads();

    // ---- layers 2 & 3: one thread per row ----
    if (tid < MT) {
        float a2[H2N];
#pragma unroll
        for (int j = 0; j < H2N; j++) a2[j] = s_b2[j];
        const float* hr = h + (size_t)tid * H_STRIDE;
#pragma unroll 4
        for (int k = 0; k < H1N; k++) {
            const float a = hr[k];
            const float4* w2r = reinterpret_cast<const float4*>(s_w2 + k * H2N);
#pragma unroll
            for (int qq = 0; qq < H2N / 4; qq++) {
                float4 w4 = w2r[qq];
                a2[qq * 4 + 0] += a * w4.x;
                a2[qq * 4 + 1] += a * w4.y;
                a2[qq * 4 + 2] += a * w4.z;
                a2[qq * 4 + 3] += a * w4.w;
            }
        }
        float o = __ldg(b3);
#pragma unroll
        for (int j = 0; j < H2N; j++)
            o += fmaxf(a2[j], 0.f) * s_w3[j];
        out[row0 + tid] = fmaxf(o, 0.f);
    }
}

// ---------------- launch (2 launches per call) ----------------
extern "C" void kernel_launch(void* const* d_in, const int* in_sizes, int n_in,
                              void* d_out, int out_size) {
    const float* x   = (const float*)d_in[0];
    const float* con = (const float*)d_in[1];
    const float* w1  = (const float*)d_in[2];
    const float* b1  = (const float*)d_in[3];
    const float* w2  = (const float*)d_in[4];
    const float* b2  = (const float*)d_in[5];
    const float* w3  = (const float*)d_in[6];
    const float* b3  = (const float*)d_in[7];
    float* out = (float*)d_out;

    cudaFuncSetAttribute(fused_mma, cudaFuncAttributeMaxDynamicSharedMemorySize, SMEM_DYN);

    prep_kernel<<<TT + (NCH * 2048 + 255) / 256, 256>>>(con, w1);
    fused_mma<<<NB / MT, NT, SMEM_DYN>>>(x, w1, b1, w2, b2, w3, b3, out);
}